// round 1
// baseline (speedup 1.0000x reference)
#include <cuda_runtime.h>
#include <math.h>

#define B_  4
#define S_  2048
#define D_  1024
#define H_  16
#define HD_ 64
#define NTOT (B_ * S_ * D_)

// Scratch (allocation-free rule: __device__ globals)
__device__ float g_q[NTOT];
__device__ float g_k[NTOT];
__device__ float g_v[NTOT];
__device__ float g_o[NTOT];

// ---------------------------------------------------------------------------
// SGEMM: C[M,N] = A[M,K] @ W[N,K]^T + bias[N]   (both operands K-major -> NT)
// 128x128 tile, BK=8, 256 threads, 8x8 per thread.
// ---------------------------------------------------------------------------
__global__ __launch_bounds__(256)
void sgemm_nt_bias(const float* __restrict__ A,
                   const float* __restrict__ W,
                   const float* __restrict__ bias,
                   float* __restrict__ C,
                   int M, int N, int K)
{
    __shared__ float As[8][128];
    __shared__ float Bs[8][128];

    const int tid  = threadIdx.x;
    const int tx   = tid & 15;
    const int ty   = tid >> 4;
    const int lrow = tid >> 1;        // 0..127
    const int lseg = (tid & 1) * 4;   // 0 or 4

    const float* Ab = A + (size_t)blockIdx.y * 128 * K;
    const float* Wb = W + (size_t)blockIdx.x * 128 * K;

    float acc[8][8];
#pragma unroll
    for (int i = 0; i < 8; i++)
#pragma unroll
        for (int j = 0; j < 8; j++) acc[i][j] = 0.f;

    for (int k0 = 0; k0 < K; k0 += 8) {
        float4 av = *(const float4*)(Ab + (size_t)lrow * K + k0 + lseg);
        float4 bv = *(const float4*)(Wb + (size_t)lrow * K + k0 + lseg);
        __syncthreads();
        As[lseg + 0][lrow] = av.x; As[lseg + 1][lrow] = av.y;
        As[lseg + 2][lrow] = av.z; As[lseg + 3][lrow] = av.w;
        Bs[lseg + 0][lrow] = bv.x; Bs[lseg + 1][lrow] = bv.y;
        Bs[lseg + 2][lrow] = bv.z; Bs[lseg + 3][lrow] = bv.w;
        __syncthreads();
#pragma unroll
        for (int kk = 0; kk < 8; kk++) {
            float a[8], b[8];
            *(float4*)&a[0] = *(const float4*)&As[kk][ty * 8];
            *(float4*)&a[4] = *(const float4*)&As[kk][ty * 8 + 4];
            *(float4*)&b[0] = *(const float4*)&Bs[kk][tx * 8];
            *(float4*)&b[4] = *(const float4*)&Bs[kk][tx * 8 + 4];
#pragma unroll
            for (int i = 0; i < 8; i++)
#pragma unroll
                for (int j = 0; j < 8; j++)
                    acc[i][j] = fmaf(a[i], b[j], acc[i][j]);
        }
    }

    const int cn = blockIdx.x * 128 + tx * 8;
#pragma unroll
    for (int i = 0; i < 8; i++) {
        int row = blockIdx.y * 128 + ty * 8 + i;
        float* Cr = C + (size_t)row * N + cn;
#pragma unroll
        for (int j = 0; j < 8; j += 4) {
            float4 v;
            v.x = acc[i][j + 0] + bias[cn + j + 0];
            v.y = acc[i][j + 1] + bias[cn + j + 1];
            v.z = acc[i][j + 2] + bias[cn + j + 2];
            v.w = acc[i][j + 3] + bias[cn + j + 3];
            *(float4*)(Cr + j) = v;
        }
    }
}

// ---------------------------------------------------------------------------
// RoPE, in place on [B*S, H, HD]. Angles computed in double so our tables are
// exact to fp32 (reference's own fp32 table error stays within tolerance).
// ---------------------------------------------------------------------------
__global__ void rope_kernel(float* __restrict__ x, int total)
{
    int idx = blockIdx.x * blockDim.x + threadIdx.x;
    if (idx >= total) return;
    int d  = idx & 31;
    int h  = (idx >> 5) & (H_ - 1);
    int bs = idx >> 9;              // / (32*16)
    int s  = bs & (S_ - 1);

    double inv = exp(-log(10000.0) * (double)d / 32.0);
    double ang = (double)s * inv;
    double sd, cd;
    sincos(ang, &sd, &cd);
    float c  = (float)cd;
    float sn = (float)sd;

    float* p = x + (size_t)bs * D_ + h * HD_ + d;
    float x1 = p[0], x2 = p[32];
    p[0]  = fmaf(x1, c, -x2 * sn);
    p[32] = fmaf(x1, sn,  x2 * c);
}

// ---------------------------------------------------------------------------
// Flash attention, fp32, causal. One CTA per (q-tile 64, head, batch).
// 256 threads (16x16), 4x4 register tile for both score and output GEMMs.
// ---------------------------------------------------------------------------
#define QS_STRIDE 68   // Qs: [hd_k][m], padded (float4-aligned, conflict-light)
#define KS_STRIDE 65   // Ks: [n][hd_k], padded (scalar reads, 65 = bank spread)
#define PS_STRIDE 68   // Ps: [m][k]

__global__ __launch_bounds__(256)
void flash_kernel(const float* __restrict__ Qg,
                  const float* __restrict__ Kg,
                  const float* __restrict__ Vg,
                  float* __restrict__ Og)
{
    extern __shared__ float sm[];
    float* Qs = sm;                        // 64*68
    float* Ks = Qs + 64 * QS_STRIDE;       // 64*65
    float* Vs = Ks + 64 * KS_STRIDE;       // 64*64  [k_seq][hd]
    float* Ps = Vs + 64 * 64;              // 64*68

    const int qt  = blockIdx.x;
    const int h   = blockIdx.y;
    const int b   = blockIdx.z;
    const int tid = threadIdx.x;
    const int tx  = tid & 15;
    const int ty  = tid >> 4;

    // Load Q tile transposed: Qs[k][m]
    const float* Qb = Qg + ((size_t)(b * S_ + qt * 64)) * D_ + h * HD_;
#pragma unroll
    for (int r = 0; r < 4; r++) {
        int id  = tid + r * 256;
        int row = id >> 4;
        int col = (id & 15) << 2;
        float4 qv = *(const float4*)(Qb + row * D_ + col);
        Qs[(col + 0) * QS_STRIDE + row] = qv.x;
        Qs[(col + 1) * QS_STRIDE + row] = qv.y;
        Qs[(col + 2) * QS_STRIDE + row] = qv.z;
        Qs[(col + 3) * QS_STRIDE + row] = qv.w;
    }

    float mi[4], li[4], o[4][4];
#pragma unroll
    for (int i = 0; i < 4; i++) {
        mi[i] = -INFINITY;
        li[i] = 0.f;
#pragma unroll
        for (int j = 0; j < 4; j++) o[i][j] = 0.f;
    }

    for (int kt = 0; kt <= qt; kt++) {
        const float* Kb = Kg + ((size_t)(b * S_ + kt * 64)) * D_ + h * HD_;
        const float* Vb = Vg + ((size_t)(b * S_ + kt * 64)) * D_ + h * HD_;
        __syncthreads();   // previous PV readers done before overwrite
#pragma unroll
        for (int r = 0; r < 4; r++) {
            int id  = tid + r * 256;
            int row = id >> 4;
            int col = (id & 15) << 2;
            float4 kv = *(const float4*)(Kb + row * D_ + col);
            Ks[row * KS_STRIDE + col + 0] = kv.x;
            Ks[row * KS_STRIDE + col + 1] = kv.y;
            Ks[row * KS_STRIDE + col + 2] = kv.z;
            Ks[row * KS_STRIDE + col + 3] = kv.w;
            float4 vv = *(const float4*)(Vb + row * D_ + col);
            *(float4*)(Vs + row * 64 + col) = vv;
        }
        __syncthreads();

        // S = Q K^T  (64x64x64)
        float sc[4][4];
#pragma unroll
        for (int i = 0; i < 4; i++)
#pragma unroll
            for (int j = 0; j < 4; j++) sc[i][j] = 0.f;

#pragma unroll 8
        for (int kk = 0; kk < 64; kk++) {
            float4 a = *(const float4*)(Qs + kk * QS_STRIDE + ty * 4);
            float b0 = Ks[(tx * 4 + 0) * KS_STRIDE + kk];
            float b1 = Ks[(tx * 4 + 1) * KS_STRIDE + kk];
            float b2 = Ks[(tx * 4 + 2) * KS_STRIDE + kk];
            float b3 = Ks[(tx * 4 + 3) * KS_STRIDE + kk];
            sc[0][0] = fmaf(a.x, b0, sc[0][0]); sc[0][1] = fmaf(a.x, b1, sc[0][1]);
            sc[0][2] = fmaf(a.x, b2, sc[0][2]); sc[0][3] = fmaf(a.x, b3, sc[0][3]);
            sc[1][0] = fmaf(a.y, b0, sc[1][0]); sc[1][1] = fmaf(a.y, b1, sc[1][1]);
            sc[1][2] = fmaf(a.y, b2, sc[1][2]); sc[1][3] = fmaf(a.y, b3, sc[1][3]);
            sc[2][0] = fmaf(a.z, b0, sc[2][0]); sc[2][1] = fmaf(a.z, b1, sc[2][1]);
            sc[2][2] = fmaf(a.z, b2, sc[2][2]); sc[2][3] = fmaf(a.z, b3, sc[2][3]);
            sc[3][0] = fmaf(a.w, b0, sc[3][0]); sc[3][1] = fmaf(a.w, b1, sc[3][1]);
            sc[3][2] = fmaf(a.w, b2, sc[3][2]); sc[3][3] = fmaf(a.w, b3, sc[3][3]);
        }

        const float scale = 0.125f;   // 1/sqrt(64)
        const bool diag = (kt == qt);
#pragma unroll
        for (int i = 0; i < 4; i++) {
            int qrow = ty * 4 + i;
#pragma unroll
            for (int j = 0; j < 4; j++) {
                float v = sc[i][j] * scale;
                if (diag && (tx * 4 + j) > qrow) v = -INFINITY;
                sc[i][j] = v;
            }
            float rm = fmaxf(fmaxf(sc[i][0], sc[i][1]), fmaxf(sc[i][2], sc[i][3]));
            rm = fmaxf(rm, __shfl_xor_sync(0xffffffffu, rm, 1));
            rm = fmaxf(rm, __shfl_xor_sync(0xffffffffu, rm, 2));
            rm = fmaxf(rm, __shfl_xor_sync(0xffffffffu, rm, 4));
            rm = fmaxf(rm, __shfl_xor_sync(0xffffffffu, rm, 8));
            float mn = fmaxf(mi[i], rm);
            float al = expf(mi[i] - mn);
            float4 pr;
            pr.x = expf(sc[i][0] - mn);
            pr.y = expf(sc[i][1] - mn);
            pr.z = expf(sc[i][2] - mn);
            pr.w = expf(sc[i][3] - mn);
            float rs = pr.x + pr.y + pr.z + pr.w;
            rs += __shfl_xor_sync(0xffffffffu, rs, 1);
            rs += __shfl_xor_sync(0xffffffffu, rs, 2);
            rs += __shfl_xor_sync(0xffffffffu, rs, 4);
            rs += __shfl_xor_sync(0xffffffffu, rs, 8);
            li[i] = li[i] * al + rs;
            mi[i] = mn;
            o[i][0] *= al; o[i][1] *= al; o[i][2] *= al; o[i][3] *= al;
            *(float4*)(Ps + (ty * 4 + i) * PS_STRIDE + tx * 4) = pr;
        }
        __syncthreads();

        // O += P @ V  (64x64x64)
#pragma unroll 8
        for (int kk = 0; kk < 64; kk++) {
            float4 bv = *(const float4*)(Vs + kk * 64 + tx * 4);
            float a0 = Ps[(ty * 4 + 0) * PS_STRIDE + kk];
            float a1 = Ps[(ty * 4 + 1) * PS_STRIDE + kk];
            float a2 = Ps[(ty * 4 + 2) * PS_STRIDE + kk];
            float a3 = Ps[(ty * 4 + 3) * PS_STRIDE + kk];
            o[0][0] = fmaf(a0, bv.x, o[0][0]); o[0][1] = fmaf(a0, bv.y, o[0][1]);
            o[0][2] = fmaf(a0, bv.z, o[0][2]); o[0][3] = fmaf(a0, bv.w, o[0][3]);
            o[1][0] = fmaf(a1, bv.x, o[1][0]); o[1][1] = fmaf(a1, bv.y, o[1][1]);
            o[1][2] = fmaf(a1, bv.z, o[1][2]); o[1][3] = fmaf(a1, bv.w, o[1][3]);
            o[2][0] = fmaf(a2, bv.x, o[2][0]); o[2][1] = fmaf(a2, bv.y, o[2][1]);
            o[2][2] = fmaf(a2, bv.z, o[2][2]); o[2][3] = fmaf(a2, bv.w, o[2][3]);
            o[3][0] = fmaf(a3, bv.x, o[3][0]); o[3][1] = fmaf(a3, bv.y, o[3][1]);
            o[3][2] = fmaf(a3, bv.z, o[3][2]); o[3][3] = fmaf(a3, bv.w, o[3][3]);
        }
    }

    // Epilogue: normalize and store to [b, s, h, hd] (== [B*S, D] for next GEMM)
#pragma unroll
    for (int i = 0; i < 4; i++) {
        float inv = 1.f / li[i];
        float4 st;
        st.x = o[i][0] * inv; st.y = o[i][1] * inv;
        st.z = o[i][2] * inv; st.w = o[i][3] * inv;
        *(float4*)(Og + ((size_t)(b * S_ + qt * 64 + ty * 4 + i)) * D_ + h * HD_ + tx * 4) = st;
    }
}

// ---------------------------------------------------------------------------
extern "C" void kernel_launch(void* const* d_in, const int* in_sizes, int n_in,
                              void* d_out, int out_size)
{
    const float* Q  = (const float*)d_in[0];
    const float* K  = (const float*)d_in[1];
    const float* V  = (const float*)d_in[2];
    const float* Wq = (const float*)d_in[3];
    const float* bq = (const float*)d_in[4];
    const float* Wk = (const float*)d_in[5];
    const float* bk = (const float*)d_in[6];
    const float* Wv = (const float*)d_in[7];
    const float* bv = (const float*)d_in[8];
    const float* Wo = (const float*)d_in[9];
    const float* bo = (const float*)d_in[10];
    float* out = (float*)d_out;

    float *gq, *gk, *gv, *go;
    cudaGetSymbolAddress((void**)&gq, g_q);
    cudaGetSymbolAddress((void**)&gk, g_k);
    cudaGetSymbolAddress((void**)&gv, g_v);
    cudaGetSymbolAddress((void**)&go, g_o);

    const int M = B_ * S_, N = D_, Kd = D_;
    dim3 ggrid(N / 128, M / 128);

    sgemm_nt_bias<<<ggrid, 256>>>(Q, Wq, bq, gq, M, N, Kd);
    sgemm_nt_bias<<<ggrid, 256>>>(K, Wk, bk, gk, M, N, Kd);
    sgemm_nt_bias<<<ggrid, 256>>>(V, Wv, bv, gv, M, N, Kd);

    int tot = B_ * S_ * H_ * 32;
    rope_kernel<<<(tot + 255) / 256, 256>>>(gq, tot);
    rope_kernel<<<(tot + 255) / 256, 256>>>(gk, tot);

    size_t fsm = (size_t)(64 * QS_STRIDE + 64 * KS_STRIDE + 64 * 64 + 64 * PS_STRIDE) * sizeof(float);
    cudaFuncSetAttribute(flash_kernel, cudaFuncAttributeMaxDynamicSharedMemorySize, (int)fsm);
    dim3 fgrid(S_ / 64, H_, B_);
    flash_kernel<<<fgrid, 256, fsm>>>(gq, gk, gv, go);

    sgemm_nt_bias<<<ggrid, 256>>>(go, Wo, bo, out, M, N, Kd);
}

// round 2
// speedup vs baseline: 1.3797x; 1.3797x over previous
#include <cuda_runtime.h>
#include <math.h>

#define B_  4
#define S_  2048
#define D_  1024
#define H_  16
#define HD_ 64
#define NTOT (B_ * S_ * D_)

// Scratch (allocation-free rule: __device__ globals)
__device__ float g_q[NTOT];
__device__ float g_k[NTOT];
__device__ float g_v[NTOT];
__device__ float g_o[NTOT];
__device__ float2 g_rope[S_ * 32];   // (cos, sin) per (s, d)

// ---------------------------------------------------------------------------
// SGEMM: C[M,N] = A[M,K] @ W[N,K]^T + bias[N]   (both operands K-major -> NT)
// 128x128 tile, BK=8, 256 threads, 8x8 per thread.
// ---------------------------------------------------------------------------
__global__ __launch_bounds__(256)
void sgemm_nt_bias(const float* __restrict__ A,
                   const float* __restrict__ W,
                   const float* __restrict__ bias,
                   float* __restrict__ C,
                   int M, int N, int K)
{
    __shared__ float As[8][128];
    __shared__ float Bs[8][128];

    const int tid  = threadIdx.x;
    const int tx   = tid & 15;
    const int ty   = tid >> 4;
    const int lrow = tid >> 1;        // 0..127
    const int lseg = (tid & 1) * 4;   // 0 or 4

    const float* Ab = A + (size_t)blockIdx.y * 128 * K;
    const float* Wb = W + (size_t)blockIdx.x * 128 * K;

    float acc[8][8];
#pragma unroll
    for (int i = 0; i < 8; i++)
#pragma unroll
        for (int j = 0; j < 8; j++) acc[i][j] = 0.f;

    for (int k0 = 0; k0 < K; k0 += 8) {
        float4 av = *(const float4*)(Ab + (size_t)lrow * K + k0 + lseg);
        float4 bv = *(const float4*)(Wb + (size_t)lrow * K + k0 + lseg);
        __syncthreads();
        As[lseg + 0][lrow] = av.x; As[lseg + 1][lrow] = av.y;
        As[lseg + 2][lrow] = av.z; As[lseg + 3][lrow] = av.w;
        Bs[lseg + 0][lrow] = bv.x; Bs[lseg + 1][lrow] = bv.y;
        Bs[lseg + 2][lrow] = bv.z; Bs[lseg + 3][lrow] = bv.w;
        __syncthreads();
#pragma unroll
        for (int kk = 0; kk < 8; kk++) {
            float a[8], b[8];
            *(float4*)&a[0] = *(const float4*)&As[kk][ty * 8];
            *(float4*)&a[4] = *(const float4*)&As[kk][ty * 8 + 4];
            *(float4*)&b[0] = *(const float4*)&Bs[kk][tx * 8];
            *(float4*)&b[4] = *(const float4*)&Bs[kk][tx * 8 + 4];
#pragma unroll
            for (int i = 0; i < 8; i++)
#pragma unroll
                for (int j = 0; j < 8; j++)
                    acc[i][j] = fmaf(a[i], b[j], acc[i][j]);
        }
    }

    const int cn = blockIdx.x * 128 + tx * 8;
#pragma unroll
    for (int i = 0; i < 8; i++) {
        int row = blockIdx.y * 128 + ty * 8 + i;
        float* Cr = C + (size_t)row * N + cn;
#pragma unroll
        for (int j = 0; j < 8; j += 4) {
            float4 v;
            v.x = acc[i][j + 0] + bias[cn + j + 0];
            v.y = acc[i][j + 1] + bias[cn + j + 1];
            v.z = acc[i][j + 2] + bias[cn + j + 2];
            v.w = acc[i][j + 3] + bias[cn + j + 3];
            *(float4*)(Cr + j) = v;
        }
    }
}

// ---------------------------------------------------------------------------
// RoPE table: one thread per (s, d) entry, fp64 math for exactness.
// ---------------------------------------------------------------------------
__global__ void rope_table_kernel(float2* __restrict__ tab)
{
    int idx = blockIdx.x * blockDim.x + threadIdx.x;
    if (idx >= S_ * 32) return;
    int s = idx >> 5;
    int d = idx & 31;
    double inv = exp(-log(10000.0) * (double)d / 32.0);
    double ang = (double)s * inv;
    double sd, cd;
    sincos(ang, &sd, &cd);
    tab[idx] = make_float2((float)cd, (float)sd);
}

// ---------------------------------------------------------------------------
// RoPE apply (Q and K in one launch). Each thread: 4 consecutive d of one
// (bs, h) row -> float4 at d and d+32. Pure memory traffic.
// ---------------------------------------------------------------------------
__global__ __launch_bounds__(256)
void rope_apply_kernel(float* __restrict__ q, float* __restrict__ k,
                       const float2* __restrict__ tab)
{
    const int half = B_ * S_ * H_ * 8;   // vec4 work items per tensor
    int idx = blockIdx.x * blockDim.x + threadIdx.x;
    if (idx >= 2 * half) return;
    float* x = (idx < half) ? q : k;
    int i = (idx < half) ? idx : idx - half;

    int dv = (i & 7) << 2;            // 0..28 step 4
    int h  = (i >> 3) & (H_ - 1);
    int bs = i >> 7;
    int s  = bs & (S_ - 1);

    float* p = x + (size_t)bs * D_ + h * HD_ + dv;
    float4 a = *(const float4*)p;          // x1
    float4 b = *(const float4*)(p + 32);   // x2
    const float2* t = tab + s * 32 + dv;
    float2 t0 = t[0], t1 = t[1], t2 = t[2], t3 = t[3];

    float4 ra, rb;
    ra.x = fmaf(a.x, t0.x, -b.x * t0.y);  rb.x = fmaf(a.x, t0.y, b.x * t0.x);
    ra.y = fmaf(a.y, t1.x, -b.y * t1.y);  rb.y = fmaf(a.y, t1.y, b.y * t1.x);
    ra.z = fmaf(a.z, t2.x, -b.z * t2.y);  rb.z = fmaf(a.z, t2.y, b.z * t2.x);
    ra.w = fmaf(a.w, t3.x, -b.w * t3.y);  rb.w = fmaf(a.w, t3.y, b.w * t3.x);

    *(float4*)p        = ra;
    *(float4*)(p + 32) = rb;
}

// ---------------------------------------------------------------------------
// Flash attention, fp32, causal. One CTA per (q-tile 64, head, batch).
// 256 threads (16x16), 4x4 register tile for both score and output GEMMs.
// ---------------------------------------------------------------------------
#define QS_STRIDE 68   // Qs: [hd_k][m], padded (float4-aligned, conflict-light)
#define KS_STRIDE 65   // Ks: [n][hd_k], padded (scalar reads, 65 = bank spread)
#define PS_STRIDE 68   // Ps: [m][k]

__global__ __launch_bounds__(256)
void flash_kernel(const float* __restrict__ Qg,
                  const float* __restrict__ Kg,
                  const float* __restrict__ Vg,
                  float* __restrict__ Og)
{
    extern __shared__ float sm[];
    float* Qs = sm;                        // 64*68
    float* Ks = Qs + 64 * QS_STRIDE;       // 64*65
    float* Vs = Ks + 64 * KS_STRIDE;       // 64*64  [k_seq][hd]
    float* Ps = Vs + 64 * 64;              // 64*68

    const int qt  = blockIdx.x;
    const int h   = blockIdx.y;
    const int b   = blockIdx.z;
    const int tid = threadIdx.x;
    const int tx  = tid & 15;
    const int ty  = tid >> 4;

    // Load Q tile transposed: Qs[k][m]
    const float* Qb = Qg + ((size_t)(b * S_ + qt * 64)) * D_ + h * HD_;
#pragma unroll
    for (int r = 0; r < 4; r++) {
        int id  = tid + r * 256;
        int row = id >> 4;
        int col = (id & 15) << 2;
        float4 qv = *(const float4*)(Qb + row * D_ + col);
        Qs[(col + 0) * QS_STRIDE + row] = qv.x;
        Qs[(col + 1) * QS_STRIDE + row] = qv.y;
        Qs[(col + 2) * QS_STRIDE + row] = qv.z;
        Qs[(col + 3) * QS_STRIDE + row] = qv.w;
    }

    float mi[4], li[4], o[4][4];
#pragma unroll
    for (int i = 0; i < 4; i++) {
        mi[i] = -INFINITY;
        li[i] = 0.f;
#pragma unroll
        for (int j = 0; j < 4; j++) o[i][j] = 0.f;
    }

    for (int kt = 0; kt <= qt; kt++) {
        const float* Kb = Kg + ((size_t)(b * S_ + kt * 64)) * D_ + h * HD_;
        const float* Vb = Vg + ((size_t)(b * S_ + kt * 64)) * D_ + h * HD_;
        __syncthreads();   // previous PV readers done before overwrite
#pragma unroll
        for (int r = 0; r < 4; r++) {
            int id  = tid + r * 256;
            int row = id >> 4;
            int col = (id & 15) << 2;
            float4 kv = *(const float4*)(Kb + row * D_ + col);
            Ks[row * KS_STRIDE + col + 0] = kv.x;
            Ks[row * KS_STRIDE + col + 1] = kv.y;
            Ks[row * KS_STRIDE + col + 2] = kv.z;
            Ks[row * KS_STRIDE + col + 3] = kv.w;
            float4 vv = *(const float4*)(Vb + row * D_ + col);
            *(float4*)(Vs + row * 64 + col) = vv;
        }
        __syncthreads();

        // S = Q K^T  (64x64x64)
        float sc[4][4];
#pragma unroll
        for (int i = 0; i < 4; i++)
#pragma unroll
            for (int j = 0; j < 4; j++) sc[i][j] = 0.f;

#pragma unroll 8
        for (int kk = 0; kk < 64; kk++) {
            float4 a = *(const float4*)(Qs + kk * QS_STRIDE + ty * 4);
            float b0 = Ks[(tx * 4 + 0) * KS_STRIDE + kk];
            float b1 = Ks[(tx * 4 + 1) * KS_STRIDE + kk];
            float b2 = Ks[(tx * 4 + 2) * KS_STRIDE + kk];
            float b3 = Ks[(tx * 4 + 3) * KS_STRIDE + kk];
            sc[0][0] = fmaf(a.x, b0, sc[0][0]); sc[0][1] = fmaf(a.x, b1, sc[0][1]);
            sc[0][2] = fmaf(a.x, b2, sc[0][2]); sc[0][3] = fmaf(a.x, b3, sc[0][3]);
            sc[1][0] = fmaf(a.y, b0, sc[1][0]); sc[1][1] = fmaf(a.y, b1, sc[1][1]);
            sc[1][2] = fmaf(a.y, b2, sc[1][2]); sc[1][3] = fmaf(a.y, b3, sc[1][3]);
            sc[2][0] = fmaf(a.z, b0, sc[2][0]); sc[2][1] = fmaf(a.z, b1, sc[2][1]);
            sc[2][2] = fmaf(a.z, b2, sc[2][2]); sc[2][3] = fmaf(a.z, b3, sc[2][3]);
            sc[3][0] = fmaf(a.w, b0, sc[3][0]); sc[3][1] = fmaf(a.w, b1, sc[3][1]);
            sc[3][2] = fmaf(a.w, b2, sc[3][2]); sc[3][3] = fmaf(a.w, b3, sc[3][3]);
        }

        const float scale = 0.125f;   // 1/sqrt(64)
        const bool diag = (kt == qt);
#pragma unroll
        for (int i = 0; i < 4; i++) {
            int qrow = ty * 4 + i;
#pragma unroll
            for (int j = 0; j < 4; j++) {
                float v = sc[i][j] * scale;
                if (diag && (tx * 4 + j) > qrow) v = -INFINITY;
                sc[i][j] = v;
            }
            float rm = fmaxf(fmaxf(sc[i][0], sc[i][1]), fmaxf(sc[i][2], sc[i][3]));
            rm = fmaxf(rm, __shfl_xor_sync(0xffffffffu, rm, 1));
            rm = fmaxf(rm, __shfl_xor_sync(0xffffffffu, rm, 2));
            rm = fmaxf(rm, __shfl_xor_sync(0xffffffffu, rm, 4));
            rm = fmaxf(rm, __shfl_xor_sync(0xffffffffu, rm, 8));
            float mn = fmaxf(mi[i], rm);
            float al = __expf(mi[i] - mn);
            float4 pr;
            pr.x = __expf(sc[i][0] - mn);
            pr.y = __expf(sc[i][1] - mn);
            pr.z = __expf(sc[i][2] - mn);
            pr.w = __expf(sc[i][3] - mn);
            float rs = pr.x + pr.y + pr.z + pr.w;
            rs += __shfl_xor_sync(0xffffffffu, rs, 1);
            rs += __shfl_xor_sync(0xffffffffu, rs, 2);
            rs += __shfl_xor_sync(0xffffffffu, rs, 4);
            rs += __shfl_xor_sync(0xffffffffu, rs, 8);
            li[i] = li[i] * al + rs;
            mi[i] = mn;
            o[i][0] *= al; o[i][1] *= al; o[i][2] *= al; o[i][3] *= al;
            *(float4*)(Ps + (ty * 4 + i) * PS_STRIDE + tx * 4) = pr;
        }
        __syncthreads();

        // O += P @ V  (64x64x64)
#pragma unroll 8
        for (int kk = 0; kk < 64; kk++) {
            float4 bv = *(const float4*)(Vs + kk * 64 + tx * 4);
            float a0 = Ps[(ty * 4 + 0) * PS_STRIDE + kk];
            float a1 = Ps[(ty * 4 + 1) * PS_STRIDE + kk];
            float a2 = Ps[(ty * 4 + 2) * PS_STRIDE + kk];
            float a3 = Ps[(ty * 4 + 3) * PS_STRIDE + kk];
            o[0][0] = fmaf(a0, bv.x, o[0][0]); o[0][1] = fmaf(a0, bv.y, o[0][1]);
            o[0][2] = fmaf(a0, bv.z, o[0][2]); o[0][3] = fmaf(a0, bv.w, o[0][3]);
            o[1][0] = fmaf(a1, bv.x, o[1][0]); o[1][1] = fmaf(a1, bv.y, o[1][1]);
            o[1][2] = fmaf(a1, bv.z, o[1][2]); o[1][3] = fmaf(a1, bv.w, o[1][3]);
            o[2][0] = fmaf(a2, bv.x, o[2][0]); o[2][1] = fmaf(a2, bv.y, o[2][1]);
            o[2][2] = fmaf(a2, bv.z, o[2][2]); o[2][3] = fmaf(a2, bv.w, o[2][3]);
            o[3][0] = fmaf(a3, bv.x, o[3][0]); o[3][1] = fmaf(a3, bv.y, o[3][1]);
            o[3][2] = fmaf(a3, bv.z, o[3][2]); o[3][3] = fmaf(a3, bv.w, o[3][3]);
        }
    }

    // Epilogue: normalize and store to [b, s, h, hd] (== [B*S, D] for next GEMM)
#pragma unroll
    for (int i = 0; i < 4; i++) {
        float inv = 1.f / li[i];
        float4 st;
        st.x = o[i][0] * inv; st.y = o[i][1] * inv;
        st.z = o[i][2] * inv; st.w = o[i][3] * inv;
        *(float4*)(Og + ((size_t)(b * S_ + qt * 64 + ty * 4 + i)) * D_ + h * HD_ + tx * 4) = st;
    }
}

// ---------------------------------------------------------------------------
extern "C" void kernel_launch(void* const* d_in, const int* in_sizes, int n_in,
                              void* d_out, int out_size)
{
    const float* Q  = (const float*)d_in[0];
    const float* K  = (const float*)d_in[1];
    const float* V  = (const float*)d_in[2];
    const float* Wq = (const float*)d_in[3];
    const float* bq = (const float*)d_in[4];
    const float* Wk = (const float*)d_in[5];
    const float* bk = (const float*)d_in[6];
    const float* Wv = (const float*)d_in[7];
    const float* bv = (const float*)d_in[8];
    const float* Wo = (const float*)d_in[9];
    const float* bo = (const float*)d_in[10];
    float* out = (float*)d_out;

    float *gq, *gk, *gv, *go;
    float2* grope;
    cudaGetSymbolAddress((void**)&gq, g_q);
    cudaGetSymbolAddress((void**)&gk, g_k);
    cudaGetSymbolAddress((void**)&gv, g_v);
    cudaGetSymbolAddress((void**)&go, g_o);
    cudaGetSymbolAddress((void**)&grope, g_rope);

    const int M = B_ * S_, N = D_, Kd = D_;
    dim3 ggrid(N / 128, M / 128);

    // RoPE table build overlaps nothing but is ~10us; launch first.
    rope_table_kernel<<<(S_ * 32 + 255) / 256, 256>>>(grope);

    sgemm_nt_bias<<<ggrid, 256>>>(Q, Wq, bq, gq, M, N, Kd);
    sgemm_nt_bias<<<ggrid, 256>>>(K, Wk, bk, gk, M, N, Kd);
    sgemm_nt_bias<<<ggrid, 256>>>(V, Wv, bv, gv, M, N, Kd);

    int items = 2 * B_ * S_ * H_ * 8;
    rope_apply_kernel<<<(items + 255) / 256, 256>>>(gq, gk, grope);

    size_t fsm = (size_t)(64 * QS_STRIDE + 64 * KS_STRIDE + 64 * 64 + 64 * PS_STRIDE) * sizeof(float);
    cudaFuncSetAttribute(flash_kernel, cudaFuncAttributeMaxDynamicSharedMemorySize, (int)fsm);
    dim3 fgrid(S_ / 64, H_, B_);
    flash_kernel<<<fgrid, 256, fsm>>>(gq, gk, gv, go);

    sgemm_nt_bias<<<ggrid, 256>>>(go, Wo, bo, out, M, N, Kd);
}

// round 4
// speedup vs baseline: 2.3940x; 1.7352x over previous
#include <cuda_runtime.h>
#include <cuda_bf16.h>
#include <math.h>
#include <stdint.h>

#define B_  4
#define S_  2048
#define D_  1024
#define H_  16
#define HD_ 64
#define M_  (B_ * S_)
#define NTOT (B_ * S_ * D_)

// Scratch (allocation-free rule: __device__ globals)
__device__ float g_q[NTOT];
__device__ float g_k[NTOT];
__device__ float g_v[NTOT];
__device__ float g_o[NTOT];
__device__ __nv_bfloat16 g_xh[NTOT];
__device__ __nv_bfloat16 g_xl[NTOT];
__device__ __nv_bfloat16 g_wh[D_ * D_];
__device__ __nv_bfloat16 g_wl[D_ * D_];
__device__ float2 g_rope[S_ * 32];

// ===========================================================================
// Helpers (baseline PTX only — compute_103-safe: ldmatrix, mma.sync, cp.async)
// ===========================================================================
__device__ __forceinline__ uint32_t smem_to_u32(const void* p) {
    uint32_t a;
    asm("{ .reg .u64 t; cvta.to.shared.u64 t, %1; cvt.u32.u64 %0, t; }" : "=r"(a) : "l"(p));
    return a;
}
#define SMEM_SWIZZLE_128B(off) ((off) ^ (((off) >> 3) & 0x70))

__device__ __forceinline__ void cpa16(uint32_t dst, const void* src) {
    asm volatile("cp.async.cg.shared.global [%0], [%1], 16;" :: "r"(dst), "l"(src));
}
__device__ __forceinline__ void ldsm4(uint32_t& r0, uint32_t& r1, uint32_t& r2, uint32_t& r3,
                                      uint32_t addr) {
    asm volatile("ldmatrix.sync.aligned.m8n8.x4.shared.b16 {%0,%1,%2,%3}, [%4];"
        : "=r"(r0), "=r"(r1), "=r"(r2), "=r"(r3) : "r"(addr));
}
__device__ __forceinline__ void mma_bf16(float* d, const uint32_t* a,
                                         uint32_t b0, uint32_t b1) {
    asm volatile(
        "mma.sync.aligned.m16n8k16.row.col.f32.bf16.bf16.f32 "
        "{%0,%1,%2,%3}, {%4,%5,%6,%7}, {%8,%9}, {%0,%1,%2,%3};"
        : "+f"(d[0]), "+f"(d[1]), "+f"(d[2]), "+f"(d[3])
        : "r"(a[0]), "r"(a[1]), "r"(a[2]), "r"(a[3]), "r"(b0), "r"(b1));
}

// ===========================================================================
// fp32 -> bf16 (hi, lo) split
// ===========================================================================
__global__ __launch_bounds__(256)
void split_kernel(const float* __restrict__ x,
                  __nv_bfloat16* __restrict__ h,
                  __nv_bfloat16* __restrict__ l, int n4)
{
    int i = blockIdx.x * blockDim.x + threadIdx.x;
    if (i >= n4) return;
    float4 v = ((const float4*)x)[i];
    __nv_bfloat16 h0 = __float2bfloat16(v.x);
    __nv_bfloat16 h1 = __float2bfloat16(v.y);
    __nv_bfloat16 h2 = __float2bfloat16(v.z);
    __nv_bfloat16 h3 = __float2bfloat16(v.w);
    __nv_bfloat16 l0 = __float2bfloat16(v.x - __bfloat162float(h0));
    __nv_bfloat16 l1 = __float2bfloat16(v.y - __bfloat162float(h1));
    __nv_bfloat16 l2 = __float2bfloat16(v.z - __bfloat162float(h2));
    __nv_bfloat16 l3 = __float2bfloat16(v.w - __bfloat162float(h3));
    ((__nv_bfloat162*)h)[2 * i + 0] = __nv_bfloat162(h0, h1);
    ((__nv_bfloat162*)h)[2 * i + 1] = __nv_bfloat162(h2, h3);
    ((__nv_bfloat162*)l)[2 * i + 0] = __nv_bfloat162(l0, l1);
    ((__nv_bfloat162*)l)[2 * i + 1] = __nv_bfloat162(l2, l3);
}

// ===========================================================================
// mma.sync bf16-split GEMM: C[M,N] = (Ah+Al)[M,K] @ (Bh+Bl)[N,K]^T + bias
// 128x128 tile, BK=64, 8 warps (64x32 each), cp.async double buffer, SW128.
// ===========================================================================
#define TILE_BYTES 16384            // 128 rows x 128 bytes (128x64 bf16)
#define STAGE_BYTES (4 * TILE_BYTES)
#define GEMM_SMEM (2 * STAGE_BYTES) // 131072
#define NCHUNK (D_ / 64)            // 16

__device__ __forceinline__ void gemm_load_chunk(
    uint32_t sb, int stage, int k0, int tid,
    const __nv_bfloat16* Ahb, const __nv_bfloat16* Alb,
    const __nv_bfloat16* Bhb, const __nv_bfloat16* Blb)
{
    uint32_t base = sb + stage * STAGE_BYTES;
#pragma unroll
    for (int rep = 0; rep < 4; rep++) {
        int id  = tid + rep * 256;
        int row = id >> 3;
        int seg = id & 7;
        uint32_t soff = SMEM_SWIZZLE_128B((uint32_t)(row * 128 + seg * 16));
        size_t goff = (size_t)row * D_ + k0 + seg * 8;
        cpa16(base + 0 * TILE_BYTES + soff, Ahb + goff);
        cpa16(base + 1 * TILE_BYTES + soff, Alb + goff);
        cpa16(base + 2 * TILE_BYTES + soff, Bhb + goff);
        cpa16(base + 3 * TILE_BYTES + soff, Blb + goff);
    }
    asm volatile("cp.async.commit_group;" ::: "memory");
}

__global__ __launch_bounds__(256, 1)
void gemm_mma(const __nv_bfloat16* __restrict__ Ah, const __nv_bfloat16* __restrict__ Al,
              const __nv_bfloat16* __restrict__ Bh, const __nv_bfloat16* __restrict__ Bl,
              const float* __restrict__ bias, float* __restrict__ C)
{
    extern __shared__ char smem[];
    uint32_t sb = smem_to_u32(smem);
    const int tid  = threadIdx.x;
    const int wid  = tid >> 5;
    const int lane = tid & 31;
    const int warp_m = wid >> 2;        // 0..1
    const int warp_n = wid & 3;         // 0..3
    const int bn = blockIdx.x, bm = blockIdx.y;

    const __nv_bfloat16* Ahb = Ah + (size_t)(bm * 128) * D_;
    const __nv_bfloat16* Alb = Al + (size_t)(bm * 128) * D_;
    const __nv_bfloat16* Bhb = Bh + (size_t)(bn * 128) * D_;
    const __nv_bfloat16* Blb = Bl + (size_t)(bn * 128) * D_;

    float acc[4][4][4];
#pragma unroll
    for (int i = 0; i < 4; i++)
#pragma unroll
        for (int j = 0; j < 4; j++)
#pragma unroll
            for (int r = 0; r < 4; r++) acc[i][j][r] = 0.f;

    // ldmatrix per-thread row indices (fixed across ksteps)
    const int mat = lane >> 3;          // 0..3
    const int mrr = lane & 7;           // row within 8x8
    // A x4: mat0 rows+0..7 kseg0, mat1 rows+8..15 kseg0, mat2 rows+0..7 kseg1, mat3 rows+8..15 kseg1
    const int a_row_off = (mat & 1) * 8 + mrr;     // within m16 tile
    const int a_ks_off  = (mat >> 1) * 16;         // byte offset within kstep
    // B x4 (two n8 tiles per load): mat0 nt0/kseg0, mat1 nt0/kseg1, mat2 nt1/kseg0, mat3 nt1/kseg1
    const int b_row_off = (mat >> 1) * 8 + mrr;    // within n16 pair
    const int b_ks_off  = (mat & 1) * 16;

    gemm_load_chunk(sb, 0, 0, tid, Ahb, Alb, Bhb, Blb);

    for (int c = 0; c < NCHUNK; c++) {
        int s = c & 1;
        if (c + 1 < NCHUNK) {
            gemm_load_chunk(sb, s ^ 1, (c + 1) * 64, tid, Ahb, Alb, Bhb, Blb);
            asm volatile("cp.async.wait_group 1;" ::: "memory");
        } else {
            asm volatile("cp.async.wait_group 0;" ::: "memory");
        }
        __syncthreads();

        uint32_t stA = sb + s * STAGE_BYTES;
#pragma unroll
        for (int ks = 0; ks < 4; ks++) {
            const int kb = ks * 32;
            uint32_t ah[4][4], al[4][4];
#pragma unroll
            for (int mt = 0; mt < 4; mt++) {
                int row = warp_m * 64 + mt * 16 + a_row_off;
                uint32_t off = SMEM_SWIZZLE_128B((uint32_t)(row * 128 + kb + a_ks_off));
                ldsm4(ah[mt][0], ah[mt][1], ah[mt][2], ah[mt][3], stA + 0 * TILE_BYTES + off);
                ldsm4(al[mt][0], al[mt][1], al[mt][2], al[mt][3], stA + 1 * TILE_BYTES + off);
            }
            uint32_t bh[2][4], bl[2][4];
#pragma unroll
            for (int p = 0; p < 2; p++) {
                int row = warp_n * 32 + p * 16 + b_row_off;
                uint32_t off = SMEM_SWIZZLE_128B((uint32_t)(row * 128 + kb + b_ks_off));
                ldsm4(bh[p][0], bh[p][1], bh[p][2], bh[p][3], stA + 2 * TILE_BYTES + off);
                ldsm4(bl[p][0], bl[p][1], bl[p][2], bl[p][3], stA + 3 * TILE_BYTES + off);
            }
#pragma unroll
            for (int mt = 0; mt < 4; mt++) {
#pragma unroll
                for (int p = 0; p < 2; p++) {
#pragma unroll
                    for (int q = 0; q < 2; q++) {
                        float* d = acc[mt][p * 2 + q];
                        mma_bf16(d, ah[mt], bh[p][q * 2], bh[p][q * 2 + 1]);
                        mma_bf16(d, ah[mt], bl[p][q * 2], bl[p][q * 2 + 1]);
                        mma_bf16(d, al[mt], bh[p][q * 2], bh[p][q * 2 + 1]);
                    }
                }
            }
        }
        __syncthreads();
    }

    // Epilogue: acc layout: thread holds rows (lane/4, lane/4+8), cols 2*(lane%4)+{0,1}
    const int rbase = bm * 128 + warp_m * 64 + (lane >> 2);
    const int cbase = bn * 128 + warp_n * 32 + (lane & 3) * 2;
#pragma unroll
    for (int mt = 0; mt < 4; mt++) {
#pragma unroll
        for (int nt = 0; nt < 4; nt++) {
            int col = cbase + nt * 8;
            float b0 = bias[col], b1 = bias[col + 1];
            float* d = acc[mt][nt];
            int r0 = rbase + mt * 16;
            float2 v0 = make_float2(d[0] + b0, d[1] + b1);
            float2 v1 = make_float2(d[2] + b0, d[3] + b1);
            *(float2*)(C + (size_t)r0 * D_ + col)       = v0;
            *(float2*)(C + (size_t)(r0 + 8) * D_ + col) = v1;
        }
    }
}

// ---------------------------------------------------------------------------
// RoPE table: one thread per (s, d) entry, fp64 math for exactness.
// ---------------------------------------------------------------------------
__global__ void rope_table_kernel(float2* __restrict__ tab)
{
    int idx = blockIdx.x * blockDim.x + threadIdx.x;
    if (idx >= S_ * 32) return;
    int s = idx >> 5;
    int d = idx & 31;
    double inv = exp(-log(10000.0) * (double)d / 32.0);
    double ang = (double)s * inv;
    double sd, cd;
    sincos(ang, &sd, &cd);
    tab[idx] = make_float2((float)cd, (float)sd);
}

// ---------------------------------------------------------------------------
// RoPE apply (Q and K in one launch), vectorized.
// ---------------------------------------------------------------------------
__global__ __launch_bounds__(256)
void rope_apply_kernel(float* __restrict__ q, float* __restrict__ k,
                       const float2* __restrict__ tab)
{
    const int half = B_ * S_ * H_ * 8;
    int idx = blockIdx.x * blockDim.x + threadIdx.x;
    if (idx >= 2 * half) return;
    float* x = (idx < half) ? q : k;
    int i = (idx < half) ? idx : idx - half;

    int dv = (i & 7) << 2;
    int h  = (i >> 3) & (H_ - 1);
    int bs = i >> 7;
    int s  = bs & (S_ - 1);

    float* p = x + (size_t)bs * D_ + h * HD_ + dv;
    float4 a = *(const float4*)p;
    float4 b = *(const float4*)(p + 32);
    const float2* t = tab + s * 32 + dv;
    float2 t0 = t[0], t1 = t[1], t2 = t[2], t3 = t[3];

    float4 ra, rb;
    ra.x = fmaf(a.x, t0.x, -b.x * t0.y);  rb.x = fmaf(a.x, t0.y, b.x * t0.x);
    ra.y = fmaf(a.y, t1.x, -b.y * t1.y);  rb.y = fmaf(a.y, t1.y, b.y * t1.x);
    ra.z = fmaf(a.z, t2.x, -b.z * t2.y);  rb.z = fmaf(a.z, t2.y, b.z * t2.x);
    ra.w = fmaf(a.w, t3.x, -b.w * t3.y);  rb.w = fmaf(a.w, t3.y, b.w * t3.x);

    *(float4*)p        = ra;
    *(float4*)(p + 32) = rb;
}

// ---------------------------------------------------------------------------
// Flash attention, fp32, causal (unchanged).
// ---------------------------------------------------------------------------
#define QS_STRIDE 68
#define KS_STRIDE 65
#define PS_STRIDE 68

__global__ __launch_bounds__(256)
void flash_kernel(const float* __restrict__ Qg,
                  const float* __restrict__ Kg,
                  const float* __restrict__ Vg,
                  float* __restrict__ Og)
{
    extern __shared__ float sm[];
    float* Qs = sm;
    float* Ks = Qs + 64 * QS_STRIDE;
    float* Vs = Ks + 64 * KS_STRIDE;
    float* Ps = Vs + 64 * 64;

    const int qt  = blockIdx.x;
    const int h   = blockIdx.y;
    const int b   = blockIdx.z;
    const int tid = threadIdx.x;
    const int tx  = tid & 15;
    const int ty  = tid >> 4;

    const float* Qb = Qg + ((size_t)(b * S_ + qt * 64)) * D_ + h * HD_;
#pragma unroll
    for (int r = 0; r < 4; r++) {
        int id  = tid + r * 256;
        int row = id >> 4;
        int col = (id & 15) << 2;
        float4 qv = *(const float4*)(Qb + row * D_ + col);
        Qs[(col + 0) * QS_STRIDE + row] = qv.x;
        Qs[(col + 1) * QS_STRIDE + row] = qv.y;
        Qs[(col + 2) * QS_STRIDE + row] = qv.z;
        Qs[(col + 3) * QS_STRIDE + row] = qv.w;
    }

    float mi[4], li[4], o[4][4];
#pragma unroll
    for (int i = 0; i < 4; i++) {
        mi[i] = -INFINITY;
        li[i] = 0.f;
#pragma unroll
        for (int j = 0; j < 4; j++) o[i][j] = 0.f;
    }

    for (int kt = 0; kt <= qt; kt++) {
        const float* Kb = Kg + ((size_t)(b * S_ + kt * 64)) * D_ + h * HD_;
        const float* Vb = Vg + ((size_t)(b * S_ + kt * 64)) * D_ + h * HD_;
        __syncthreads();
#pragma unroll
        for (int r = 0; r < 4; r++) {
            int id  = tid + r * 256;
            int row = id >> 4;
            int col = (id & 15) << 2;
            float4 kv = *(const float4*)(Kb + row * D_ + col);
            Ks[row * KS_STRIDE + col + 0] = kv.x;
            Ks[row * KS_STRIDE + col + 1] = kv.y;
            Ks[row * KS_STRIDE + col + 2] = kv.z;
            Ks[row * KS_STRIDE + col + 3] = kv.w;
            float4 vv = *(const float4*)(Vb + row * D_ + col);
            *(float4*)(Vs + row * 64 + col) = vv;
        }
        __syncthreads();

        float sc[4][4];
#pragma unroll
        for (int i = 0; i < 4; i++)
#pragma unroll
            for (int j = 0; j < 4; j++) sc[i][j] = 0.f;

#pragma unroll 8
        for (int kk = 0; kk < 64; kk++) {
            float4 a = *(const float4*)(Qs + kk * QS_STRIDE + ty * 4);
            float b0 = Ks[(tx * 4 + 0) * KS_STRIDE + kk];
            float b1 = Ks[(tx * 4 + 1) * KS_STRIDE + kk];
            float b2 = Ks[(tx * 4 + 2) * KS_STRIDE + kk];
            float b3 = Ks[(tx * 4 + 3) * KS_STRIDE + kk];
            sc[0][0] = fmaf(a.x, b0, sc[0][0]); sc[0][1] = fmaf(a.x, b1, sc[0][1]);
            sc[0][2] = fmaf(a.x, b2, sc[0][2]); sc[0][3] = fmaf(a.x, b3, sc[0][3]);
            sc[1][0] = fmaf(a.y, b0, sc[1][0]); sc[1][1] = fmaf(a.y, b1, sc[1][1]);
            sc[1][2] = fmaf(a.y, b2, sc[1][2]); sc[1][3] = fmaf(a.y, b3, sc[1][3]);
            sc[2][0] = fmaf(a.z, b0, sc[2][0]); sc[2][1] = fmaf(a.z, b1, sc[2][1]);
            sc[2][2] = fmaf(a.z, b2, sc[2][2]); sc[2][3] = fmaf(a.z, b3, sc[2][3]);
            sc[3][0] = fmaf(a.w, b0, sc[3][0]); sc[3][1] = fmaf(a.w, b1, sc[3][1]);
            sc[3][2] = fmaf(a.w, b2, sc[3][2]); sc[3][3] = fmaf(a.w, b3, sc[3][3]);
        }

        const float scale = 0.125f;
        const bool diag = (kt == qt);
#pragma unroll
        for (int i = 0; i < 4; i++) {
            int qrow = ty * 4 + i;
#pragma unroll
            for (int j = 0; j < 4; j++) {
                float v = sc[i][j] * scale;
                if (diag && (tx * 4 + j) > qrow) v = -INFINITY;
                sc[i][j] = v;
            }
            float rm = fmaxf(fmaxf(sc[i][0], sc[i][1]), fmaxf(sc[i][2], sc[i][3]));
            rm = fmaxf(rm, __shfl_xor_sync(0xffffffffu, rm, 1));
            rm = fmaxf(rm, __shfl_xor_sync(0xffffffffu, rm, 2));
            rm = fmaxf(rm, __shfl_xor_sync(0xffffffffu, rm, 4));
            rm = fmaxf(rm, __shfl_xor_sync(0xffffffffu, rm, 8));
            float mn = fmaxf(mi[i], rm);
            float al = __expf(mi[i] - mn);
            float4 pr;
            pr.x = __expf(sc[i][0] - mn);
            pr.y = __expf(sc[i][1] - mn);
            pr.z = __expf(sc[i][2] - mn);
            pr.w = __expf(sc[i][3] - mn);
            float rs = pr.x + pr.y + pr.z + pr.w;
            rs += __shfl_xor_sync(0xffffffffu, rs, 1);
            rs += __shfl_xor_sync(0xffffffffu, rs, 2);
            rs += __shfl_xor_sync(0xffffffffu, rs, 4);
            rs += __shfl_xor_sync(0xffffffffu, rs, 8);
            li[i] = li[i] * al + rs;
            mi[i] = mn;
            o[i][0] *= al; o[i][1] *= al; o[i][2] *= al; o[i][3] *= al;
            *(float4*)(Ps + (ty * 4 + i) * PS_STRIDE + tx * 4) = pr;
        }
        __syncthreads();

#pragma unroll 8
        for (int kk = 0; kk < 64; kk++) {
            float4 bv = *(const float4*)(Vs + kk * 64 + tx * 4);
            float a0 = Ps[(ty * 4 + 0) * PS_STRIDE + kk];
            float a1 = Ps[(ty * 4 + 1) * PS_STRIDE + kk];
            float a2 = Ps[(ty * 4 + 2) * PS_STRIDE + kk];
            float a3 = Ps[(ty * 4 + 3) * PS_STRIDE + kk];
            o[0][0] = fmaf(a0, bv.x, o[0][0]); o[0][1] = fmaf(a0, bv.y, o[0][1]);
            o[0][2] = fmaf(a0, bv.z, o[0][2]); o[0][3] = fmaf(a0, bv.w, o[0][3]);
            o[1][0] = fmaf(a1, bv.x, o[1][0]); o[1][1] = fmaf(a1, bv.y, o[1][1]);
            o[1][2] = fmaf(a1, bv.z, o[1][2]); o[1][3] = fmaf(a1, bv.w, o[1][3]);
            o[2][0] = fmaf(a2, bv.x, o[2][0]); o[2][1] = fmaf(a2, bv.y, o[2][1]);
            o[2][2] = fmaf(a2, bv.z, o[2][2]); o[2][3] = fmaf(a2, bv.w, o[2][3]);
            o[3][0] = fmaf(a3, bv.x, o[3][0]); o[3][1] = fmaf(a3, bv.y, o[3][1]);
            o[3][2] = fmaf(a3, bv.z, o[3][2]); o[3][3] = fmaf(a3, bv.w, o[3][3]);
        }
    }

#pragma unroll
    for (int i = 0; i < 4; i++) {
        float inv = 1.f / li[i];
        float4 st;
        st.x = o[i][0] * inv; st.y = o[i][1] * inv;
        st.z = o[i][2] * inv; st.w = o[i][3] * inv;
        *(float4*)(Og + ((size_t)(b * S_ + qt * 64 + ty * 4 + i)) * D_ + h * HD_ + tx * 4) = st;
    }
}

// ---------------------------------------------------------------------------
extern "C" void kernel_launch(void* const* d_in, const int* in_sizes, int n_in,
                              void* d_out, int out_size)
{
    const float* Q  = (const float*)d_in[0];
    const float* K  = (const float*)d_in[1];
    const float* V  = (const float*)d_in[2];
    const float* Wq = (const float*)d_in[3];
    const float* bq = (const float*)d_in[4];
    const float* Wk = (const float*)d_in[5];
    const float* bk = (const float*)d_in[6];
    const float* Wv = (const float*)d_in[7];
    const float* bv = (const float*)d_in[8];
    const float* Wo = (const float*)d_in[9];
    const float* bo = (const float*)d_in[10];
    float* out = (float*)d_out;

    float *gq, *gk, *gv, *go;
    float2* grope;
    __nv_bfloat16 *gxh, *gxl, *gwh, *gwl;
    cudaGetSymbolAddress((void**)&gq, g_q);
    cudaGetSymbolAddress((void**)&gk, g_k);
    cudaGetSymbolAddress((void**)&gv, g_v);
    cudaGetSymbolAddress((void**)&go, g_o);
    cudaGetSymbolAddress((void**)&grope, g_rope);
    cudaGetSymbolAddress((void**)&gxh, g_xh);
    cudaGetSymbolAddress((void**)&gxl, g_xl);
    cudaGetSymbolAddress((void**)&gwh, g_wh);
    cudaGetSymbolAddress((void**)&gwl, g_wl);

    cudaFuncSetAttribute(gemm_mma, cudaFuncAttributeMaxDynamicSharedMemorySize, GEMM_SMEM);

    const int n4x = NTOT / 4;
    const int n4w = (D_ * D_) / 4;
    dim3 ggrid(D_ / 128, M_ / 128);

    rope_table_kernel<<<(S_ * 32 + 255) / 256, 256>>>(grope);

    // Q projection
    split_kernel<<<(n4x + 255) / 256, 256>>>(Q, gxh, gxl, n4x);
    split_kernel<<<(n4w + 255) / 256, 256>>>(Wq, gwh, gwl, n4w);
    gemm_mma<<<ggrid, 256, GEMM_SMEM>>>(gxh, gxl, gwh, gwl, bq, gq);
    // K projection
    split_kernel<<<(n4x + 255) / 256, 256>>>(K, gxh, gxl, n4x);
    split_kernel<<<(n4w + 255) / 256, 256>>>(Wk, gwh, gwl, n4w);
    gemm_mma<<<ggrid, 256, GEMM_SMEM>>>(gxh, gxl, gwh, gwl, bk, gk);
    // V projection
    split_kernel<<<(n4x + 255) / 256, 256>>>(V, gxh, gxl, n4x);
    split_kernel<<<(n4w + 255) / 256, 256>>>(Wv, gwh, gwl, n4w);
    gemm_mma<<<ggrid, 256, GEMM_SMEM>>>(gxh, gxl, gwh, gwl, bv, gv);

    int items = 2 * B_ * S_ * H_ * 8;
    rope_apply_kernel<<<(items + 255) / 256, 256>>>(gq, gk, grope);

    size_t fsm = (size_t)(64 * QS_STRIDE + 64 * KS_STRIDE + 64 * 64 + 64 * PS_STRIDE) * sizeof(float);
    cudaFuncSetAttribute(flash_kernel, cudaFuncAttributeMaxDynamicSharedMemorySize, (int)fsm);
    dim3 fgrid(S_ / 64, H_, B_);
    flash_kernel<<<fgrid, 256, fsm>>>(gq, gk, gv, go);

    // Output projection
    split_kernel<<<(n4x + 255) / 256, 256>>>(go, gxh, gxl, n4x);
    split_kernel<<<(n4w + 255) / 256, 256>>>(Wo, gwh, gwl, n4w);
    gemm_mma<<<ggrid, 256, GEMM_SMEM>>>(gxh, gxl, gwh, gwl, bo, out);
}

// round 5
// speedup vs baseline: 4.2280x; 1.7660x over previous
#include <cuda_runtime.h>
#include <cuda_bf16.h>
#include <math.h>
#include <stdint.h>

#define B_  4
#define S_  2048
#define D_  1024
#define H_  16
#define HD_ 64
#define M_  (B_ * S_)
#define NTOT (B_ * S_ * D_)

// Scratch (allocation-free rule: __device__ globals)
__device__ float g_q[NTOT];
__device__ float g_k[NTOT];
__device__ float g_v[NTOT];
__device__ float g_o[NTOT];
__device__ __nv_bfloat16 g_xh[NTOT];
__device__ __nv_bfloat16 g_xl[NTOT];
__device__ __nv_bfloat16 g_wh[D_ * D_];
__device__ __nv_bfloat16 g_wl[D_ * D_];
__device__ __nv_bfloat16 g_qh[NTOT];
__device__ __nv_bfloat16 g_ql[NTOT];
__device__ __nv_bfloat16 g_kh[NTOT];
__device__ __nv_bfloat16 g_kl[NTOT];
__device__ __nv_bfloat16 g_vh[NTOT];
__device__ __nv_bfloat16 g_vl[NTOT];
__device__ float2 g_rope[S_ * 32];

// ===========================================================================
// Helpers (baseline PTX only — compute_103-safe)
// ===========================================================================
__device__ __forceinline__ uint32_t smem_to_u32(const void* p) {
    uint32_t a;
    asm("{ .reg .u64 t; cvta.to.shared.u64 t, %1; cvt.u32.u64 %0, t; }" : "=r"(a) : "l"(p));
    return a;
}
#define SMEM_SWIZZLE_128B(off) ((off) ^ (((off) >> 3) & 0x70))

__device__ __forceinline__ void cpa16(uint32_t dst, const void* src) {
    asm volatile("cp.async.cg.shared.global [%0], [%1], 16;" :: "r"(dst), "l"(src));
}
__device__ __forceinline__ void ldsm4(uint32_t& r0, uint32_t& r1, uint32_t& r2, uint32_t& r3,
                                      uint32_t addr) {
    asm volatile("ldmatrix.sync.aligned.m8n8.x4.shared.b16 {%0,%1,%2,%3}, [%4];"
        : "=r"(r0), "=r"(r1), "=r"(r2), "=r"(r3) : "r"(addr));
}
__device__ __forceinline__ void ldsm4t(uint32_t& r0, uint32_t& r1, uint32_t& r2, uint32_t& r3,
                                       uint32_t addr) {
    asm volatile("ldmatrix.sync.aligned.m8n8.x4.trans.shared.b16 {%0,%1,%2,%3}, [%4];"
        : "=r"(r0), "=r"(r1), "=r"(r2), "=r"(r3) : "r"(addr));
}
__device__ __forceinline__ void mma_bf16(float* d, const uint32_t* a,
                                         uint32_t b0, uint32_t b1) {
    asm volatile(
        "mma.sync.aligned.m16n8k16.row.col.f32.bf16.bf16.f32 "
        "{%0,%1,%2,%3}, {%4,%5,%6,%7}, {%8,%9}, {%0,%1,%2,%3};"
        : "+f"(d[0]), "+f"(d[1]), "+f"(d[2]), "+f"(d[3])
        : "r"(a[0]), "r"(a[1]), "r"(a[2]), "r"(a[3]), "r"(b0), "r"(b1));
}
__device__ __forceinline__ void split2(float f0, float f1, uint32_t& hi, uint32_t& lo) {
    __nv_bfloat16 h0 = __float2bfloat16(f0), h1 = __float2bfloat16(f1);
    __nv_bfloat16 l0 = __float2bfloat16(f0 - __bfloat162float(h0));
    __nv_bfloat16 l1 = __float2bfloat16(f1 - __bfloat162float(h1));
    __nv_bfloat162 Hh(h0, h1), Ll(l0, l1);
    hi = *(uint32_t*)&Hh; lo = *(uint32_t*)&Ll;
}

// ===========================================================================
// fp32 -> bf16 (hi, lo) split
// ===========================================================================
__global__ __launch_bounds__(256)
void split_kernel(const float* __restrict__ x,
                  __nv_bfloat16* __restrict__ h,
                  __nv_bfloat16* __restrict__ l, int n4)
{
    int i = blockIdx.x * blockDim.x + threadIdx.x;
    if (i >= n4) return;
    float4 v = ((const float4*)x)[i];
    uint32_t h01, l01, h23, l23;
    split2(v.x, v.y, h01, l01);
    split2(v.z, v.w, h23, l23);
    ((uint32_t*)h)[2 * i + 0] = h01;
    ((uint32_t*)h)[2 * i + 1] = h23;
    ((uint32_t*)l)[2 * i + 0] = l01;
    ((uint32_t*)l)[2 * i + 1] = l23;
}

// ===========================================================================
// mma.sync bf16-split GEMM (unchanged from round 4 — proven)
// ===========================================================================
#define TILE_BYTES 16384
#define STAGE_BYTES (4 * TILE_BYTES)
#define GEMM_SMEM (2 * STAGE_BYTES)
#define NCHUNK (D_ / 64)

__device__ __forceinline__ void gemm_load_chunk(
    uint32_t sb, int stage, int k0, int tid,
    const __nv_bfloat16* Ahb, const __nv_bfloat16* Alb,
    const __nv_bfloat16* Bhb, const __nv_bfloat16* Blb)
{
    uint32_t base = sb + stage * STAGE_BYTES;
#pragma unroll
    for (int rep = 0; rep < 4; rep++) {
        int id  = tid + rep * 256;
        int row = id >> 3;
        int seg = id & 7;
        uint32_t soff = SMEM_SWIZZLE_128B((uint32_t)(row * 128 + seg * 16));
        size_t goff = (size_t)row * D_ + k0 + seg * 8;
        cpa16(base + 0 * TILE_BYTES + soff, Ahb + goff);
        cpa16(base + 1 * TILE_BYTES + soff, Alb + goff);
        cpa16(base + 2 * TILE_BYTES + soff, Bhb + goff);
        cpa16(base + 3 * TILE_BYTES + soff, Blb + goff);
    }
    asm volatile("cp.async.commit_group;" ::: "memory");
}

__global__ __launch_bounds__(256, 1)
void gemm_mma(const __nv_bfloat16* __restrict__ Ah, const __nv_bfloat16* __restrict__ Al,
              const __nv_bfloat16* __restrict__ Bh, const __nv_bfloat16* __restrict__ Bl,
              const float* __restrict__ bias, float* __restrict__ C)
{
    extern __shared__ char smem[];
    uint32_t sb = smem_to_u32(smem);
    const int tid  = threadIdx.x;
    const int wid  = tid >> 5;
    const int lane = tid & 31;
    const int warp_m = wid >> 2;
    const int warp_n = wid & 3;
    const int bn = blockIdx.x, bm = blockIdx.y;

    const __nv_bfloat16* Ahb = Ah + (size_t)(bm * 128) * D_;
    const __nv_bfloat16* Alb = Al + (size_t)(bm * 128) * D_;
    const __nv_bfloat16* Bhb = Bh + (size_t)(bn * 128) * D_;
    const __nv_bfloat16* Blb = Bl + (size_t)(bn * 128) * D_;

    float acc[4][4][4];
#pragma unroll
    for (int i = 0; i < 4; i++)
#pragma unroll
        for (int j = 0; j < 4; j++)
#pragma unroll
            for (int r = 0; r < 4; r++) acc[i][j][r] = 0.f;

    const int mat = lane >> 3;
    const int mrr = lane & 7;
    const int a_row_off = (mat & 1) * 8 + mrr;
    const int a_ks_off  = (mat >> 1) * 16;
    const int b_row_off = (mat >> 1) * 8 + mrr;
    const int b_ks_off  = (mat & 1) * 16;

    gemm_load_chunk(sb, 0, 0, tid, Ahb, Alb, Bhb, Blb);

    for (int c = 0; c < NCHUNK; c++) {
        int s = c & 1;
        if (c + 1 < NCHUNK) {
            gemm_load_chunk(sb, s ^ 1, (c + 1) * 64, tid, Ahb, Alb, Bhb, Blb);
            asm volatile("cp.async.wait_group 1;" ::: "memory");
        } else {
            asm volatile("cp.async.wait_group 0;" ::: "memory");
        }
        __syncthreads();

        uint32_t stA = sb + s * STAGE_BYTES;
#pragma unroll
        for (int ks = 0; ks < 4; ks++) {
            const int kb = ks * 32;
            uint32_t ah[4][4], al[4][4];
#pragma unroll
            for (int mt = 0; mt < 4; mt++) {
                int row = warp_m * 64 + mt * 16 + a_row_off;
                uint32_t off = SMEM_SWIZZLE_128B((uint32_t)(row * 128 + kb + a_ks_off));
                ldsm4(ah[mt][0], ah[mt][1], ah[mt][2], ah[mt][3], stA + 0 * TILE_BYTES + off);
                ldsm4(al[mt][0], al[mt][1], al[mt][2], al[mt][3], stA + 1 * TILE_BYTES + off);
            }
            uint32_t bh[2][4], bl[2][4];
#pragma unroll
            for (int p = 0; p < 2; p++) {
                int row = warp_n * 32 + p * 16 + b_row_off;
                uint32_t off = SMEM_SWIZZLE_128B((uint32_t)(row * 128 + kb + b_ks_off));
                ldsm4(bh[p][0], bh[p][1], bh[p][2], bh[p][3], stA + 2 * TILE_BYTES + off);
                ldsm4(bl[p][0], bl[p][1], bl[p][2], bl[p][3], stA + 3 * TILE_BYTES + off);
            }
#pragma unroll
            for (int mt = 0; mt < 4; mt++) {
#pragma unroll
                for (int p = 0; p < 2; p++) {
#pragma unroll
                    for (int q = 0; q < 2; q++) {
                        float* d = acc[mt][p * 2 + q];
                        mma_bf16(d, ah[mt], bh[p][q * 2], bh[p][q * 2 + 1]);
                        mma_bf16(d, ah[mt], bl[p][q * 2], bl[p][q * 2 + 1]);
                        mma_bf16(d, al[mt], bh[p][q * 2], bh[p][q * 2 + 1]);
                    }
                }
            }
        }
        __syncthreads();
    }

    const int rbase = bm * 128 + warp_m * 64 + (lane >> 2);
    const int cbase = bn * 128 + warp_n * 32 + (lane & 3) * 2;
#pragma unroll
    for (int mt = 0; mt < 4; mt++) {
#pragma unroll
        for (int nt = 0; nt < 4; nt++) {
            int col = cbase + nt * 8;
            float b0 = bias[col], b1 = bias[col + 1];
            float* d = acc[mt][nt];
            int r0 = rbase + mt * 16;
            *(float2*)(C + (size_t)r0 * D_ + col)       = make_float2(d[0] + b0, d[1] + b1);
            *(float2*)(C + (size_t)(r0 + 8) * D_ + col) = make_float2(d[2] + b0, d[3] + b1);
        }
    }
}

// ---------------------------------------------------------------------------
// RoPE table (fp64 for exactness)
// ---------------------------------------------------------------------------
__global__ void rope_table_kernel(float2* __restrict__ tab)
{
    int idx = blockIdx.x * blockDim.x + threadIdx.x;
    if (idx >= S_ * 32) return;
    int s = idx >> 5;
    int d = idx & 31;
    double inv = exp(-log(10000.0) * (double)d / 32.0);
    double ang = (double)s * inv;
    double sd, cd;
    sincos(ang, &sd, &cd);
    tab[idx] = make_float2((float)cd, (float)sd);
}

// ---------------------------------------------------------------------------
// Fused RoPE + bf16 hi/lo split for Q and K: fp32 in, bf16 h/l out.
// ---------------------------------------------------------------------------
__global__ __launch_bounds__(256)
void rope_split_kernel(const float* __restrict__ q, const float* __restrict__ k,
                       const float2* __restrict__ tab,
                       __nv_bfloat16* __restrict__ qh, __nv_bfloat16* __restrict__ ql,
                       __nv_bfloat16* __restrict__ kh, __nv_bfloat16* __restrict__ kl)
{
    const int half = B_ * S_ * H_ * 8;
    int idx = blockIdx.x * blockDim.x + threadIdx.x;
    if (idx >= 2 * half) return;
    const float* x = (idx < half) ? q : k;
    __nv_bfloat16* oh = (idx < half) ? qh : kh;
    __nv_bfloat16* ol = (idx < half) ? ql : kl;
    int i = (idx < half) ? idx : idx - half;

    int dv = (i & 7) << 2;
    int h  = (i >> 3) & (H_ - 1);
    int bs = i >> 7;
    int s  = bs & (S_ - 1);

    size_t base = (size_t)bs * D_ + h * HD_ + dv;
    const float* p = x + base;
    float4 a = *(const float4*)p;
    float4 b = *(const float4*)(p + 32);
    const float2* t = tab + s * 32 + dv;
    float2 t0 = t[0], t1 = t[1], t2 = t[2], t3 = t[3];

    float4 ra, rb;
    ra.x = fmaf(a.x, t0.x, -b.x * t0.y);  rb.x = fmaf(a.x, t0.y, b.x * t0.x);
    ra.y = fmaf(a.y, t1.x, -b.y * t1.y);  rb.y = fmaf(a.y, t1.y, b.y * t1.x);
    ra.z = fmaf(a.z, t2.x, -b.z * t2.y);  rb.z = fmaf(a.z, t2.y, b.z * t2.x);
    ra.w = fmaf(a.w, t3.x, -b.w * t3.y);  rb.w = fmaf(a.w, t3.y, b.w * t3.x);

    uint32_t h01, l01, h23, l23;
    split2(ra.x, ra.y, h01, l01); split2(ra.z, ra.w, h23, l23);
    *(uint32_t*)(oh + base)     = h01;  *(uint32_t*)(oh + base + 2) = h23;
    *(uint32_t*)(ol + base)     = l01;  *(uint32_t*)(ol + base + 2) = l23;
    split2(rb.x, rb.y, h01, l01); split2(rb.z, rb.w, h23, l23);
    *(uint32_t*)(oh + base + 32) = h01; *(uint32_t*)(oh + base + 34) = h23;
    *(uint32_t*)(ol + base + 32) = l01; *(uint32_t*)(ol + base + 34) = l23;
}

// ===========================================================================
// Tensor-core flash attention. BM=128 (8 warps x m16), BN=64, HD=64.
// Q/K hi-lo split (3 MMAs), P/V hi-lo split (3 MMAs). P stays in registers.
// ===========================================================================
#define FQH 0
#define FQL 16384
#define FST 32768
#define FKH 0
#define FKL 8192
#define FVH 16384
#define FVL 24576
#define FSTAGE 32768
#define FLASH_SMEM (32768 + 2 * FSTAGE)   // 98304

__device__ __forceinline__ void flash_load_kv(
    uint32_t sb, int stage, int kt, int tid,
    const __nv_bfloat16* Khb, const __nv_bfloat16* Klb,
    const __nv_bfloat16* Vhb, const __nv_bfloat16* Vlb)
{
    uint32_t base = sb + FST + stage * FSTAGE;
    size_t rbase = (size_t)(kt * 64) * D_;
#pragma unroll
    for (int rep = 0; rep < 2; rep++) {
        int id  = tid + rep * 256;
        int row = id >> 3;
        int seg = id & 7;
        uint32_t soff = SMEM_SWIZZLE_128B((uint32_t)(row * 128 + seg * 16));
        size_t goff = rbase + (size_t)row * D_ + seg * 8;
        cpa16(base + FKH + soff, Khb + goff);
        cpa16(base + FKL + soff, Klb + goff);
        cpa16(base + FVH + soff, Vhb + goff);
        cpa16(base + FVL + soff, Vlb + goff);
    }
    asm volatile("cp.async.commit_group;" ::: "memory");
}

__global__ __launch_bounds__(256, 1)
void flash_mma(const __nv_bfloat16* __restrict__ Qh_g, const __nv_bfloat16* __restrict__ Ql_g,
               const __nv_bfloat16* __restrict__ Kh_g, const __nv_bfloat16* __restrict__ Kl_g,
               const __nv_bfloat16* __restrict__ Vh_g, const __nv_bfloat16* __restrict__ Vl_g,
               float* __restrict__ Og)
{
    extern __shared__ char smem[];
    uint32_t sb = smem_to_u32(smem);
    const int tid  = threadIdx.x;
    const int wid  = tid >> 5;
    const int lane = tid & 31;
    const int qt = blockIdx.x, h = blockIdx.y, b = blockIdx.z;

    const int g = lane >> 2, c = lane & 3;
    const int mat = lane >> 3, mrr = lane & 7;
    const int a_row_off = (mat & 1) * 8 + mrr;
    const int a_ks_off  = (mat >> 1) * 16;
    const int b_row_off = (mat >> 1) * 8 + mrr;
    const int b_ks_off  = (mat & 1) * 16;
    const int v_l = lane & 7, v_half = (lane >> 3) & 1, v_quad = lane >> 4;

    const size_t hoff = (size_t)(b * S_) * D_ + h * HD_;
    const __nv_bfloat16* Qhb = Qh_g + hoff + (size_t)(qt * 128) * D_;
    const __nv_bfloat16* Qlb = Ql_g + hoff + (size_t)(qt * 128) * D_;
    const __nv_bfloat16* Khb = Kh_g + hoff;
    const __nv_bfloat16* Klb = Kl_g + hoff;
    const __nv_bfloat16* Vhb = Vh_g + hoff;
    const __nv_bfloat16* Vlb = Vl_g + hoff;

    // Q tile load (once): 128 rows x 128 B, hi+lo
#pragma unroll
    for (int rep = 0; rep < 4; rep++) {
        int id  = tid + rep * 256;
        int row = id >> 3;
        int seg = id & 7;
        uint32_t soff = SMEM_SWIZZLE_128B((uint32_t)(row * 128 + seg * 16));
        size_t goff = (size_t)row * D_ + seg * 8;
        cpa16(sb + FQH + soff, Qhb + goff);
        cpa16(sb + FQL + soff, Qlb + goff);
    }
    asm volatile("cp.async.commit_group;" ::: "memory");

    flash_load_kv(sb, 0, 0, tid, Khb, Klb, Vhb, Vlb);
    asm volatile("cp.async.wait_group 0;" ::: "memory");
    __syncthreads();

    // Q fragments (held in registers for the whole CTA lifetime)
    uint32_t qhf[4][4], qlf[4][4];
#pragma unroll
    for (int t = 0; t < 4; t++) {
        int rowA = wid * 16 + a_row_off;
        uint32_t off = SMEM_SWIZZLE_128B((uint32_t)(rowA * 128 + t * 32 + a_ks_off));
        ldsm4(qhf[t][0], qhf[t][1], qhf[t][2], qhf[t][3], sb + FQH + off);
        ldsm4(qlf[t][0], qlf[t][1], qlf[t][2], qlf[t][3], sb + FQL + off);
    }

    float mi0 = -INFINITY, mi1 = -INFINITY, li0 = 0.f, li1 = 0.f;
    float o[8][4];
#pragma unroll
    for (int j = 0; j < 8; j++)
#pragma unroll
        for (int r = 0; r < 4; r++) o[j][r] = 0.f;

    const int wrow = qt * 128 + wid * 16;
    const int ktmax = 2 * qt + 1;

    for (int kt = 0; kt <= ktmax; kt++) {
        int s = kt & 1;
        if (kt < ktmax) {
            flash_load_kv(sb, s ^ 1, kt + 1, tid, Khb, Klb, Vhb, Vlb);
            asm volatile("cp.async.wait_group 1;" ::: "memory");
        } else {
            asm volatile("cp.async.wait_group 0;" ::: "memory");
        }
        __syncthreads();

        if (kt * 64 <= wrow + 15) {   // warp has visible columns in this tile
            uint32_t st = sb + FST + s * FSTAGE;
            float sc[8][4];
#pragma unroll
            for (int j = 0; j < 8; j++)
#pragma unroll
                for (int r = 0; r < 4; r++) sc[j][r] = 0.f;

            // S = Q K^T (hi/lo split)
#pragma unroll
            for (int t = 0; t < 4; t++) {
#pragma unroll
                for (int p = 0; p < 4; p++) {
                    uint32_t kh4[4], kl4[4];
                    int rowB = p * 16 + b_row_off;
                    uint32_t off = SMEM_SWIZZLE_128B((uint32_t)(rowB * 128 + t * 32 + b_ks_off));
                    ldsm4(kh4[0], kh4[1], kh4[2], kh4[3], st + FKH + off);
                    ldsm4(kl4[0], kl4[1], kl4[2], kl4[3], st + FKL + off);
#pragma unroll
                    for (int q = 0; q < 2; q++) {
                        float* d = sc[2 * p + q];
                        mma_bf16(d, qhf[t], kh4[q * 2], kh4[q * 2 + 1]);
                        mma_bf16(d, qhf[t], kl4[q * 2], kl4[q * 2 + 1]);
                        mma_bf16(d, qlf[t], kh4[q * 2], kh4[q * 2 + 1]);
                    }
                }
            }

            // scale + causal mask
            const float scale = 0.125f;
            const int row0 = wrow + g, row1 = row0 + 8;
            const bool diag = (kt * 64 + 63 > wrow);
#pragma unroll
            for (int j = 0; j < 8; j++) {
                int col0 = kt * 64 + j * 8 + 2 * c, col1 = col0 + 1;
                sc[j][0] *= scale; sc[j][1] *= scale;
                sc[j][2] *= scale; sc[j][3] *= scale;
                if (diag) {
                    if (col0 > row0) sc[j][0] = -INFINITY;
                    if (col1 > row0) sc[j][1] = -INFINITY;
                    if (col0 > row1) sc[j][2] = -INFINITY;
                    if (col1 > row1) sc[j][3] = -INFINITY;
                }
            }
            // row max (4 lanes per row: reduce over lane%4)
            float rm0 = -INFINITY, rm1 = -INFINITY;
#pragma unroll
            for (int j = 0; j < 8; j++) {
                rm0 = fmaxf(rm0, fmaxf(sc[j][0], sc[j][1]));
                rm1 = fmaxf(rm1, fmaxf(sc[j][2], sc[j][3]));
            }
            rm0 = fmaxf(rm0, __shfl_xor_sync(0xffffffffu, rm0, 1));
            rm0 = fmaxf(rm0, __shfl_xor_sync(0xffffffffu, rm0, 2));
            rm1 = fmaxf(rm1, __shfl_xor_sync(0xffffffffu, rm1, 1));
            rm1 = fmaxf(rm1, __shfl_xor_sync(0xffffffffu, rm1, 2));

            float mn0 = fmaxf(mi0, rm0), mn1 = fmaxf(mi1, rm1);
            float al0 = __expf(mi0 - mn0), al1 = __expf(mi1 - mn1);
            float rs0 = 0.f, rs1 = 0.f;
#pragma unroll
            for (int j = 0; j < 8; j++) {
                sc[j][0] = __expf(sc[j][0] - mn0);
                sc[j][1] = __expf(sc[j][1] - mn0);
                sc[j][2] = __expf(sc[j][2] - mn1);
                sc[j][3] = __expf(sc[j][3] - mn1);
                rs0 += sc[j][0] + sc[j][1];
                rs1 += sc[j][2] + sc[j][3];
            }
            rs0 += __shfl_xor_sync(0xffffffffu, rs0, 1);
            rs0 += __shfl_xor_sync(0xffffffffu, rs0, 2);
            rs1 += __shfl_xor_sync(0xffffffffu, rs1, 1);
            rs1 += __shfl_xor_sync(0xffffffffu, rs1, 2);
            li0 = li0 * al0 + rs0; li1 = li1 * al1 + rs1;
            mi0 = mn0; mi1 = mn1;
#pragma unroll
            for (int j = 0; j < 8; j++) {
                o[j][0] *= al0; o[j][1] *= al0;
                o[j][2] *= al1; o[j][3] *= al1;
            }

            // pack P into hi/lo A-fragments (D-frag layout == A-frag layout)
            uint32_t ph[4][4], pl[4][4];
#pragma unroll
            for (int t = 0; t < 4; t++) {
                split2(sc[2 * t][0],     sc[2 * t][1],     ph[t][0], pl[t][0]);
                split2(sc[2 * t][2],     sc[2 * t][3],     ph[t][1], pl[t][1]);
                split2(sc[2 * t + 1][0], sc[2 * t + 1][1], ph[t][2], pl[t][2]);
                split2(sc[2 * t + 1][2], sc[2 * t + 1][3], ph[t][3], pl[t][3]);
            }

            // O += P V (hi/lo split), V via ldmatrix.trans
#pragma unroll
            for (int t = 0; t < 4; t++) {
#pragma unroll
                for (int jp = 0; jp < 4; jp++) {
                    uint32_t soff = SMEM_SWIZZLE_128B(
                        (uint32_t)((16 * t + v_half * 8 + v_l) * 128 + jp * 32 + v_quad * 16));
                    uint32_t vh4[4], vl4[4];
                    ldsm4t(vh4[0], vh4[1], vh4[2], vh4[3], st + FVH + soff);
                    ldsm4t(vl4[0], vl4[1], vl4[2], vl4[3], st + FVL + soff);
                    float* d0 = o[2 * jp];
                    float* d1 = o[2 * jp + 1];
                    mma_bf16(d0, ph[t], vh4[0], vh4[1]);
                    mma_bf16(d0, ph[t], vl4[0], vl4[1]);
                    mma_bf16(d0, pl[t], vh4[0], vh4[1]);
                    mma_bf16(d1, ph[t], vh4[2], vh4[3]);
                    mma_bf16(d1, ph[t], vl4[2], vl4[3]);
                    mma_bf16(d1, pl[t], vh4[2], vh4[3]);
                }
            }
        }
        __syncthreads();
    }

    // epilogue
    float iv0 = 1.f / li0, iv1 = 1.f / li1;
    float* O0 = Og + ((size_t)(b * S_ + wrow + g)) * D_ + h * HD_;
    float* O1 = O0 + 8 * D_;
#pragma unroll
    for (int j = 0; j < 8; j++) {
        int col = j * 8 + 2 * c;
        *(float2*)(O0 + col) = make_float2(o[j][0] * iv0, o[j][1] * iv0);
        *(float2*)(O1 + col) = make_float2(o[j][2] * iv1, o[j][3] * iv1);
    }
}

// ---------------------------------------------------------------------------
extern "C" void kernel_launch(void* const* d_in, const int* in_sizes, int n_in,
                              void* d_out, int out_size)
{
    const float* Q  = (const float*)d_in[0];
    const float* K  = (const float*)d_in[1];
    const float* V  = (const float*)d_in[2];
    const float* Wq = (const float*)d_in[3];
    const float* bq = (const float*)d_in[4];
    const float* Wk = (const float*)d_in[5];
    const float* bk = (const float*)d_in[6];
    const float* Wv = (const float*)d_in[7];
    const float* bv = (const float*)d_in[8];
    const float* Wo = (const float*)d_in[9];
    const float* bo = (const float*)d_in[10];
    float* out = (float*)d_out;

    float *gq, *gk, *gv, *go;
    float2* grope;
    __nv_bfloat16 *gxh, *gxl, *gwh, *gwl;
    __nv_bfloat16 *gqh, *gql, *gkh, *gkl, *gvh, *gvl;
    cudaGetSymbolAddress((void**)&gq, g_q);
    cudaGetSymbolAddress((void**)&gk, g_k);
    cudaGetSymbolAddress((void**)&gv, g_v);
    cudaGetSymbolAddress((void**)&go, g_o);
    cudaGetSymbolAddress((void**)&grope, g_rope);
    cudaGetSymbolAddress((void**)&gxh, g_xh);
    cudaGetSymbolAddress((void**)&gxl, g_xl);
    cudaGetSymbolAddress((void**)&gwh, g_wh);
    cudaGetSymbolAddress((void**)&gwl, g_wl);
    cudaGetSymbolAddress((void**)&gqh, g_qh);
    cudaGetSymbolAddress((void**)&gql, g_ql);
    cudaGetSymbolAddress((void**)&gkh, g_kh);
    cudaGetSymbolAddress((void**)&gkl, g_kl);
    cudaGetSymbolAddress((void**)&gvh, g_vh);
    cudaGetSymbolAddress((void**)&gvl, g_vl);

    cudaFuncSetAttribute(gemm_mma, cudaFuncAttributeMaxDynamicSharedMemorySize, GEMM_SMEM);
    cudaFuncSetAttribute(flash_mma, cudaFuncAttributeMaxDynamicSharedMemorySize, FLASH_SMEM);

    const int n4x = NTOT / 4;
    const int n4w = (D_ * D_) / 4;
    dim3 ggrid(D_ / 128, M_ / 128);

    rope_table_kernel<<<(S_ * 32 + 255) / 256, 256>>>(grope);

    split_kernel<<<(n4x + 255) / 256, 256>>>(Q, gxh, gxl, n4x);
    split_kernel<<<(n4w + 255) / 256, 256>>>(Wq, gwh, gwl, n4w);
    gemm_mma<<<ggrid, 256, GEMM_SMEM>>>(gxh, gxl, gwh, gwl, bq, gq);

    split_kernel<<<(n4x + 255) / 256, 256>>>(K, gxh, gxl, n4x);
    split_kernel<<<(n4w + 255) / 256, 256>>>(Wk, gwh, gwl, n4w);
    gemm_mma<<<ggrid, 256, GEMM_SMEM>>>(gxh, gxl, gwh, gwl, bk, gk);

    split_kernel<<<(n4x + 255) / 256, 256>>>(V, gxh, gxl, n4x);
    split_kernel<<<(n4w + 255) / 256, 256>>>(Wv, gwh, gwl, n4w);
    gemm_mma<<<ggrid, 256, GEMM_SMEM>>>(gxh, gxl, gwh, gwl, bv, gv);

    // RoPE + split Q,K ; split V
    int items = 2 * B_ * S_ * H_ * 8;
    rope_split_kernel<<<(items + 255) / 256, 256>>>(gq, gk, grope, gqh, gql, gkh, gkl);
    split_kernel<<<(n4x + 255) / 256, 256>>>(gv, gvh, gvl, n4x);

    dim3 fgrid(S_ / 128, H_, B_);
    flash_mma<<<fgrid, 256, FLASH_SMEM>>>(gqh, gql, gkh, gkl, gvh, gvl, go);

    split_kernel<<<(n4x + 255) / 256, 256>>>(go, gxh, gxl, n4x);
    split_kernel<<<(n4w + 255) / 256, 256>>>(Wo, gwh, gwl, n4w);
    gemm_mma<<<ggrid, 256, GEMM_SMEM>>>(gxh, gxl, gwh, gwl, bo, out);
}